// round 11
// baseline (speedup 1.0000x reference)
#include <cuda_runtime.h>
#include <cuda_fp16.h>
#include <cstdint>

// Problem dims
#define TOKS 4096
#define HID  4096
#define INTER 14336
#define GSZ  64

// SwiGLU intermediate scaling to keep fp16 in range
#define H_SCALE   (1.0f/256.0f)
#define H_UNSCALE (256.0f)

// ---------------------------------------------------------------------------
// Device scratch
// ---------------------------------------------------------------------------
__device__ __half g_w1h[(size_t)INTER * HID];
__device__ __half g_w3h[(size_t)INTER * HID];
__device__ __half g_w2h[(size_t)HID * INTER];
__device__ __half g_xh [(size_t)TOKS * HID];
__device__ __half g_hh [(size_t)TOKS * INTER];

// ---------------------------------------------------------------------------
// PTX helpers (sm_100-base-safe: cp.async, ldmatrix, mma.sync)
// ---------------------------------------------------------------------------
static __device__ __forceinline__ uint32_t smem_u32(const void* p) {
    return (uint32_t)__cvta_generic_to_shared(p);
}
static __device__ __forceinline__ void cp16(void* s, const void* g) {
    asm volatile("cp.async.cg.shared.global [%0], [%1], 16;\n"
                 :: "r"(smem_u32(s)), "l"(g));
}
static __device__ __forceinline__ void cp_commit() {
    asm volatile("cp.async.commit_group;\n");
}
template <int N>
static __device__ __forceinline__ void cp_wait() {
    asm volatile("cp.async.wait_group %0;\n" :: "n"(N));
}
static __device__ __forceinline__ void ldsm_x4u(uint32_t* r, uint32_t addr) {
    asm volatile("ldmatrix.sync.aligned.m8n8.x4.shared.b16 {%0,%1,%2,%3}, [%4];\n"
                 : "=r"(r[0]), "=r"(r[1]), "=r"(r[2]), "=r"(r[3])
                 : "r"(addr));
}
static __device__ __forceinline__ void mma_16816(float* c, const uint32_t* a,
                                                 uint32_t b0, uint32_t b1) {
    asm volatile("mma.sync.aligned.m16n8k16.row.col.f32.f16.f16.f32 "
                 "{%0,%1,%2,%3}, {%4,%5,%6,%7}, {%8,%9}, {%0,%1,%2,%3};\n"
                 : "+f"(c[0]), "+f"(c[1]), "+f"(c[2]), "+f"(c[3])
                 : "r"(a[0]), "r"(a[1]), "r"(a[2]), "r"(a[3]),
                   "r"(b0), "r"(b1));
}
static __device__ __forceinline__ float silu_f(float x) {
    return x / (1.0f + __expf(-x));
}

// ---------------------------------------------------------------------------
// Dequant (grid-stride): int32 codes + per-group scale/zero -> fp16
// ---------------------------------------------------------------------------
__global__ void k_dequant(const int* __restrict__ q,
                          const float* __restrict__ sc,
                          const float* __restrict__ zp,
                          __half* __restrict__ out,
                          int cols, int gpc, int total8)
{
    const int stride = gridDim.x * blockDim.x;
    for (int i = blockIdx.x * blockDim.x + threadIdx.x; i < total8; i += stride) {
        int base = i * 8;
        int row  = base / cols;
        int col  = base - row * cols;
        int gi   = row * gpc + (col >> 6);
        float s = sc[gi];
        float z = zp[gi];
        const int4* qp = reinterpret_cast<const int4*>(q + base);
        int4 qa = qp[0];
        int4 qb = qp[1];
        __half2 p0 = __floats2half2_rn(((float)qa.x - z) * s, ((float)qa.y - z) * s);
        __half2 p1 = __floats2half2_rn(((float)qa.z - z) * s, ((float)qa.w - z) * s);
        __half2 p2 = __floats2half2_rn(((float)qb.x - z) * s, ((float)qb.y - z) * s);
        __half2 p3 = __floats2half2_rn(((float)qb.z - z) * s, ((float)qb.w - z) * s);
        uint4 o;
        o.x = *reinterpret_cast<uint32_t*>(&p0);
        o.y = *reinterpret_cast<uint32_t*>(&p1);
        o.z = *reinterpret_cast<uint32_t*>(&p2);
        o.w = *reinterpret_cast<uint32_t*>(&p3);
        *reinterpret_cast<uint4*>(out + base) = o;
    }
}

__global__ void k_xconv(const float* __restrict__ x, int total4)
{
    const int stride = gridDim.x * blockDim.x;
    for (int i = blockIdx.x * blockDim.x + threadIdx.x; i < total4; i += stride) {
        float4 v = reinterpret_cast<const float4*>(x)[i];
        __half2 a = __floats2half2_rn(v.x, v.y);
        __half2 b = __floats2half2_rn(v.z, v.w);
        uint2 o;
        o.x = *reinterpret_cast<uint32_t*>(&a);
        o.y = *reinterpret_cast<uint32_t*>(&b);
        reinterpret_cast<uint2*>(g_xh)[i] = o;
    }
}

// ---------------------------------------------------------------------------
// GEMM1 (fused gate+up): G = X*W1^T, U = X*W3^T, H = silu(G)*U*H_SCALE
// CTA: 128 threads, tile M128 x N64 per matrix, BK=64, STG=2, 2 CTAs/SM.
// 4 warps 2(M)x2(N); warp tile M64 x N32 per matrix. (Round-10 best config.)
// ---------------------------------------------------------------------------
namespace g1 {
constexpr int BM = 128, BN = 64, BK = 64, LDK = 72, STG = 2;
constexpr int SA = BM * LDK;              // 9216 halves
constexpr int SB = BN * LDK;              // 4608 halves
constexpr int SSTAGE = SA + 2 * SB;       // 18432 halves
constexpr int STAGE_B = SSTAGE * 2;       // 36864 bytes
constexpr int SMEM_BYTES = STG * STAGE_B; // 73728
}

__global__ void __launch_bounds__(128, 2) k_gemm1()
{
    using namespace g1;
    extern __shared__ __half sm[];
    const int tid  = threadIdx.x;
    const int lane = tid & 31;
    const int warp = tid >> 5;
    const int m0 = blockIdx.x * BM;   // m fastest -> B-tile L2 reuse
    const int n0 = blockIdx.y * BN;
    const int wm = (warp & 1) * 64;
    const int wn = (warp >> 1) * 32;

    float acc1[4][4][4] = {};
    float acc3[4][4][4] = {};

    auto load_stage = [&](int s, int kt) {
        const int k0 = kt * BK;
        __half* sA  = sm + s * SSTAGE;
        __half* sB1 = sA + SA;
        __half* sB3 = sB1 + SB;
#pragma unroll
        for (int i = 0; i < 8; i++) {
            int c = tid + i * 128;
            int r = c >> 3, kc = c & 7;
            cp16(sA + r * LDK + kc * 8,
                 g_xh + (size_t)(m0 + r) * HID + k0 + kc * 8);
        }
#pragma unroll
        for (int i = 0; i < 4; i++) {
            int c = tid + i * 128;
            int r = c >> 3, kc = c & 7;
            cp16(sB1 + r * LDK + kc * 8,
                 g_w1h + (size_t)(n0 + r) * HID + k0 + kc * 8);
        }
#pragma unroll
        for (int i = 0; i < 4; i++) {
            int c = tid + i * 128;
            int r = c >> 3, kc = c & 7;
            cp16(sB3 + r * LDK + kc * 8,
                 g_w3h + (size_t)(n0 + r) * HID + k0 + kc * 8);
        }
    };

    const uint32_t smb = smem_u32(sm);
    const int a_row = lane & 15;
    const int a_col = (lane >> 4) * 8;
    const int g = lane >> 3;
    const int b_row = (g & 1) * 8 + (lane & 7);
    const int b_col = (g >> 1) * 8;
    uint32_t a_off[4], b1_off[2], b3_off[2];
#pragma unroll
    for (int mi = 0; mi < 4; mi++)
        a_off[mi] = smb + ((wm + mi * 16 + a_row) * LDK + a_col) * 2;
#pragma unroll
    for (int nj = 0; nj < 2; nj++) {
        uint32_t ro = ((wn + nj * 16 + b_row) * LDK + b_col) * 2;
        b1_off[nj] = smb + SA * 2 + ro;
        b3_off[nj] = smb + (SA + SB) * 2 + ro;
    }

    const int KT = HID / BK;  // 64
    load_stage(0, 0);
    cp_commit();

    for (int kt = 0; kt < KT; ++kt) {
        cp_wait<0>();
        __syncthreads();
        if (kt + 1 < KT) load_stage((kt + 1) & 1, kt + 1);
        cp_commit();

        const uint32_t sbase = (kt & 1) * (uint32_t)STAGE_B;
#pragma unroll
        for (int kk16 = 0; kk16 < 4; kk16++) {
            const uint32_t ko = sbase + (uint32_t)kk16 * 32;
            uint32_t af[4][4];
#pragma unroll
            for (int mi = 0; mi < 4; mi++)
                ldsm_x4u(af[mi], a_off[mi] + ko);
            uint32_t b1f[2][4], b3f[2][4];
#pragma unroll
            for (int nj = 0; nj < 2; nj++) {
                ldsm_x4u(b1f[nj], b1_off[nj] + ko);
                ldsm_x4u(b3f[nj], b3_off[nj] + ko);
            }
#pragma unroll
            for (int mi = 0; mi < 4; mi++)
#pragma unroll
                for (int nj = 0; nj < 2; nj++) {
                    mma_16816(acc1[mi][2 * nj],     af[mi], b1f[nj][0], b1f[nj][2]);
                    mma_16816(acc3[mi][2 * nj],     af[mi], b3f[nj][0], b3f[nj][2]);
                    mma_16816(acc1[mi][2 * nj + 1], af[mi], b1f[nj][1], b1f[nj][3]);
                    mma_16816(acc3[mi][2 * nj + 1], af[mi], b3f[nj][1], b3f[nj][3]);
                }
        }
    }

    // Epilogue: SwiGLU, scale, store fp16 H
#pragma unroll
    for (int mi = 0; mi < 4; mi++) {
#pragma unroll
        for (int nt = 0; nt < 4; nt++) {
            const float* a1 = acc1[mi][nt];
            const float* a3 = acc3[mi][nt];
            int row = m0 + wm + mi * 16 + (lane >> 2);
            int col = n0 + wn + nt * 8 + 2 * (lane & 3);
            float h0 = silu_f(a1[0]) * a3[0] * H_SCALE;
            float h1 = silu_f(a1[1]) * a3[1] * H_SCALE;
            float h2 = silu_f(a1[2]) * a3[2] * H_SCALE;
            float h3 = silu_f(a1[3]) * a3[3] * H_SCALE;
            __half2 lo = __floats2half2_rn(h0, h1);
            __half2 hi = __floats2half2_rn(h2, h3);
            *reinterpret_cast<__half2*>(g_hh + (size_t)row * INTER + col) = lo;
            *reinterpret_cast<__half2*>(g_hh + (size_t)(row + 8) * INTER + col) = hi;
        }
    }
}

// ---------------------------------------------------------------------------
// GEMM2 (down proj): OUT = H * W2^T * H_UNSCALE
// CTA: 128 threads, tile M128 x N128, BK=64, STG=2, 2 CTAs/SM.
// 4 warps 2(M)x2(N); warp tile 64x64. (Round-10 best config.)
// ---------------------------------------------------------------------------
namespace g2 {
constexpr int BM = 128, BN = 128, BK = 64, LDK = 72, STG = 2;
constexpr int SA = BM * LDK;
constexpr int SB = BN * LDK;
constexpr int SSTAGE = SA + SB;
constexpr int STAGE_B = SSTAGE * 2;       // 36864 bytes
constexpr int SMEM_BYTES = STG * STAGE_B; // 73728
}

__global__ void __launch_bounds__(128, 2) k_gemm2(float* __restrict__ out)
{
    using namespace g2;
    extern __shared__ __half sm[];
    const int tid  = threadIdx.x;
    const int lane = tid & 31;
    const int warp = tid >> 5;
    const int m0 = blockIdx.x * BM;
    const int n0 = blockIdx.y * BN;
    const int wm = (warp & 1) * 64;
    const int wn = (warp >> 1) * 64;

    float acc[4][8][4] = {};

    auto load_stage = [&](int s, int kt) {
        const int k0 = kt * BK;
        __half* sA = sm + s * SSTAGE;
        __half* sB = sA + SA;
#pragma unroll
        for (int i = 0; i < 8; i++) {
            int c = tid + i * 128;
            int r = c >> 3, kc = c & 7;
            cp16(sA + r * LDK + kc * 8,
                 g_hh + (size_t)(m0 + r) * INTER + k0 + kc * 8);
        }
#pragma unroll
        for (int i = 0; i < 8; i++) {
            int c = tid + i * 128;
            int r = c >> 3, kc = c & 7;
            cp16(sB + r * LDK + kc * 8,
                 g_w2h + (size_t)(n0 + r) * INTER + k0 + kc * 8);
        }
    };

    const uint32_t smb = smem_u32(sm);
    const int a_row = lane & 15;
    const int a_col = (lane >> 4) * 8;
    const int g = lane >> 3;
    const int b_row = (g & 1) * 8 + (lane & 7);
    const int b_col = (g >> 1) * 8;
    uint32_t a_off[4], b_off[4];
#pragma unroll
    for (int mi = 0; mi < 4; mi++)
        a_off[mi] = smb + ((wm + mi * 16 + a_row) * LDK + a_col) * 2;
#pragma unroll
    for (int nj = 0; nj < 4; nj++)
        b_off[nj] = smb + SA * 2 + ((wn + nj * 16 + b_row) * LDK + b_col) * 2;

    const int KT = INTER / BK;  // 224
    load_stage(0, 0);
    cp_commit();

    for (int kt = 0; kt < KT; ++kt) {
        cp_wait<0>();
        __syncthreads();
        if (kt + 1 < KT) load_stage((kt + 1) & 1, kt + 1);
        cp_commit();

        const uint32_t sbase = (kt & 1) * (uint32_t)STAGE_B;
#pragma unroll
        for (int kk16 = 0; kk16 < 4; kk16++) {
            const uint32_t ko = sbase + (uint32_t)kk16 * 32;
            uint32_t af[4][4];
#pragma unroll
            for (int mi = 0; mi < 4; mi++)
                ldsm_x4u(af[mi], a_off[mi] + ko);
            uint32_t bf[4][4];
#pragma unroll
            for (int nj = 0; nj < 4; nj++)
                ldsm_x4u(bf[nj], b_off[nj] + ko);
#pragma unroll
            for (int mi = 0; mi < 4; mi++)
#pragma unroll
                for (int nj = 0; nj < 4; nj++) {
                    mma_16816(acc[mi][2 * nj],     af[mi], bf[nj][0], bf[nj][2]);
                    mma_16816(acc[mi][2 * nj + 1], af[mi], bf[nj][1], bf[nj][3]);
                }
        }
    }

#pragma unroll
    for (int mi = 0; mi < 4; mi++) {
#pragma unroll
        for (int nt = 0; nt < 8; nt++) {
            const float* a = acc[mi][nt];
            int row = m0 + wm + mi * 16 + (lane >> 2);
            int col = n0 + wn + nt * 8 + 2 * (lane & 3);
            float2 lo = make_float2(a[0] * H_UNSCALE, a[1] * H_UNSCALE);
            float2 hi = make_float2(a[2] * H_UNSCALE, a[3] * H_UNSCALE);
            *reinterpret_cast<float2*>(out + (size_t)row * HID + col) = lo;
            *reinterpret_cast<float2*>(out + (size_t)(row + 8) * HID + col) = hi;
        }
    }
}

// ---------------------------------------------------------------------------
// Launch. W2 dequant forked to a side stream so it overlaps gemm1
// (canonical capture-legal fork/join via events; streams/events are created
// and destroyed per call — host ops, no device allocation).
// ---------------------------------------------------------------------------
extern "C" void kernel_launch(void* const* d_in, const int* in_sizes, int n_in,
                              void* d_out, int out_size)
{
    (void)in_sizes; (void)n_in; (void)out_size;
    const float* x   = (const float*)d_in[0];
    const int*   w1q = (const int*)  d_in[1];
    const float* w1s = (const float*)d_in[2];
    const float* w1z = (const float*)d_in[3];
    const int*   w3q = (const int*)  d_in[4];
    const float* w3s = (const float*)d_in[5];
    const float* w3z = (const float*)d_in[6];
    const int*   w2q = (const int*)  d_in[7];
    const float* w2s = (const float*)d_in[8];
    const float* w2z = (const float*)d_in[9];
    float* out = (float*)d_out;

    void* p;
    cudaGetSymbolAddress(&p, g_w1h); __half* w1h = (__half*)p;
    cudaGetSymbolAddress(&p, g_w3h); __half* w3h = (__half*)p;
    cudaGetSymbolAddress(&p, g_w2h); __half* w2h = (__half*)p;

    cudaFuncSetAttribute(k_gemm1, cudaFuncAttributeMaxDynamicSharedMemorySize,
                         g1::SMEM_BYTES);
    cudaFuncSetAttribute(k_gemm2, cudaFuncAttributeMaxDynamicSharedMemorySize,
                         g2::SMEM_BYTES);

    const int t8 = INTER * HID / 8;
    const int t4 = TOKS * HID / 4;
    const int GS_BLOCKS = 148 * 8;   // grid-stride persistent-ish blocks

    // Side stream + fork/join events (created per call; host-side ops are
    // legal during stream capture).
    cudaStream_t s1;
    cudaStreamCreateWithFlags(&s1, cudaStreamNonBlocking);
    cudaEvent_t eFork, eJoin;
    cudaEventCreateWithFlags(&eFork, cudaEventDisableTiming);
    cudaEventCreateWithFlags(&eJoin, cudaEventDisableTiming);

    // GEMM1 inputs on the main (captured) stream
    k_dequant<<<GS_BLOCKS, 256>>>(w1q, w1s, w1z, w1h, HID, HID / GSZ, t8);
    k_dequant<<<GS_BLOCKS, 256>>>(w3q, w3s, w3z, w3h, HID, HID / GSZ, t8);
    k_xconv<<<GS_BLOCKS, 256>>>(x, t4);

    // Fork: W2 dequant runs on s1, concurrent with gemm1
    cudaEventRecord(eFork, 0);
    cudaStreamWaitEvent(s1, eFork, 0);
    k_dequant<<<GS_BLOCKS, 256, 0, s1>>>(w2q, w2s, w2z, w2h, INTER, INTER / GSZ, t8);
    cudaEventRecord(eJoin, s1);

    // GEMM1 (gate/up + SwiGLU) — overlaps W2 dequant
    k_gemm1<<<dim3(TOKS / g1::BM, INTER / g1::BN), 128, g1::SMEM_BYTES>>>();

    // Join: gemm2 needs both gemm1 (same stream) and W2 (event)
    cudaStreamWaitEvent(0, eJoin, 0);
    k_gemm2<<<dim3(TOKS / g2::BM, HID / g2::BN), 128, g2::SMEM_BYTES>>>(out);

    cudaEventDestroy(eFork);
    cudaEventDestroy(eJoin);
    cudaStreamDestroy(s1);
}